// round 9
// baseline (speedup 1.0000x reference)
#include <cuda_runtime.h>
#include <math.h>

#define N_NODES 100000
#define N_EDGES 3200000
#define CAP 96          // max in-degree slots (Poisson(32): P(deg>96) ~ 1e-20)

// Scratch (static device globals; no allocation). Max stride 16 floats.
__device__ __align__(128) float g_bufA[(size_t)N_NODES * 16];
__device__ __align__(128) float g_bufB[(size_t)N_NODES * 16];
__device__ int    g_cursor[N_NODES];
// +CAP padding: unconditional prefetch may read past the last node's bin
__device__ __align__(128) float2 g_edges[(size_t)(N_NODES + 1) * CAP];

// ---------------------------------------------------------------------------
// Layer-1 dense MM: s1[100000,12] = x[100000,512] @ W1[512,12]  (stride 16 out)
// ---------------------------------------------------------------------------
__global__ void mm1_kernel(const float* __restrict__ x,
                           const float* __restrict__ W,
                           float* __restrict__ out) {
    __shared__ float sW[512 * 13];
    for (int i = threadIdx.x; i < 512 * 12; i += blockDim.x) {
        int k = i / 12, j = i % 12;
        sW[k * 13 + j] = W[i];
    }
    __syncthreads();

    int warp = (blockIdx.x * blockDim.x + threadIdx.x) >> 5;
    int lane = threadIdx.x & 31;
    if (warp >= N_NODES) return;

    const float4* xr = reinterpret_cast<const float4*>(x + (size_t)warp * 512);
    float acc[12];
#pragma unroll
    for (int j = 0; j < 12; j++) acc[j] = 0.f;

#pragma unroll
    for (int it = 0; it < 4; it++) {
        int k4 = it * 32 + lane;
        float4 xv = xr[k4];
        int k = k4 * 4;
#pragma unroll
        for (int j = 0; j < 12; j++) {
            acc[j] = fmaf(xv.x, sW[(k + 0) * 13 + j], acc[j]);
            acc[j] = fmaf(xv.y, sW[(k + 1) * 13 + j], acc[j]);
            acc[j] = fmaf(xv.z, sW[(k + 2) * 13 + j], acc[j]);
            acc[j] = fmaf(xv.w, sW[(k + 3) * 13 + j], acc[j]);
        }
    }
#pragma unroll
    for (int j = 0; j < 12; j++) {
#pragma unroll
        for (int o = 16; o > 0; o >>= 1)
            acc[j] += __shfl_down_sync(0xffffffffu, acc[j], o);
    }
    if (lane == 0) {
        float* o = out + (size_t)warp * 16;
#pragma unroll
        for (int j = 0; j < 12; j++) o[j] = acc[j];
    }
}

// ---------------------------------------------------------------------------
// Bin edges by destination, 4 edges per thread (vector index loads).
// ---------------------------------------------------------------------------
__global__ void fill_bins_kernel(const float* __restrict__ ev,
                                 const int* __restrict__ src,
                                 const int* __restrict__ dst) {
    int t = blockIdx.x * blockDim.x + threadIdx.x;
    int e = t * 4;
    if (e + 4 <= N_EDGES) {
        float4 v4 = *reinterpret_cast<const float4*>(ev + e);
        int4 s4 = *reinterpret_cast<const int4*>(src + e);
        int4 d4 = *reinterpret_cast<const int4*>(dst + e);
        int p0 = atomicAdd(&g_cursor[d4.x], 1);
        int p1 = atomicAdd(&g_cursor[d4.y], 1);
        int p2 = atomicAdd(&g_cursor[d4.z], 1);
        int p3 = atomicAdd(&g_cursor[d4.w], 1);
        if (p0 < CAP) g_edges[(size_t)d4.x * CAP + p0] = make_float2(v4.x, __int_as_float(s4.x));
        if (p1 < CAP) g_edges[(size_t)d4.y * CAP + p1] = make_float2(v4.y, __int_as_float(s4.y));
        if (p2 < CAP) g_edges[(size_t)d4.z * CAP + p2] = make_float2(v4.z, __int_as_float(s4.z));
        if (p3 < CAP) g_edges[(size_t)d4.w * CAP + p3] = make_float2(v4.w, __int_as_float(s4.w));
    } else {
        for (; e < N_EDGES; e++) {
            int d = dst[e];
            int pos = atomicAdd(&g_cursor[d], 1);
            if (pos < CAP)
                g_edges[(size_t)d * CAP + pos] = make_float2(ev[e], __int_as_float(src[e]));
        }
    }
}

// ---------------------------------------------------------------------------
// Fused gather + epilogue. SUB lanes per node, lane j owns feature j.
// Edge list consumed as float4 (2 edges each), 8-edge software pipeline:
// next iteration's 4 elist float4s prefetched (streaming .cs) before this
// iteration's 8 independent row loads. 32-bit row offsets.
// Epilogue: h = ACT(agg [+ bpre]); out = GEMM ? h@W [+ bpost] : h.
// ACT: 0=id, 1=relu, 2=tanhshrink
// ---------------------------------------------------------------------------
template <int DIN, int SUB, int SIN, int DOUT, int SOUT,
          int ACT, bool BPRE, bool GEMM, bool BPOST>
__global__ void __launch_bounds__(256, 4)
gather_kernel(const float* __restrict__ s,
              const float* __restrict__ W,
              const float* __restrict__ bpre,
              const float* __restrict__ bpost,
              float* __restrict__ out) {
    constexpr int NPW = 32 / SUB;   // nodes per warp
    __shared__ float sW[GEMM ? DIN * DOUT : 1];
    __shared__ float sbpre[DIN];
    __shared__ float sbpost[BPOST ? DOUT : 1];
    __shared__ float sh[8][NPW][SUB];

    if (GEMM)
        for (int i = threadIdx.x; i < DIN * DOUT; i += blockDim.x) sW[i] = W[i];
    if (BPRE && threadIdx.x < DIN) sbpre[threadIdx.x] = bpre[threadIdx.x];
    if (BPOST && threadIdx.x < DOUT) sbpost[threadIdx.x] = bpost[threadIdx.x];
    __syncthreads();

    const int warpid = threadIdx.x >> 5;
    const int lane = threadIdx.x & 31;
    const int sub = lane / SUB;          // node slot within warp (const shift)
    const int j = lane & (SUB - 1);      // owned feature
    const int node = ((blockIdx.x * blockDim.x + threadIdx.x) >> 5) * NPW + sub;
    const bool valid = node < N_NODES;

    int deg = 0;
    if (valid) {
        deg = g_cursor[node];
        deg = deg < CAP ? deg : CAP;
    }

    const float4* el4 = reinterpret_cast<const float4*>(&g_edges[(size_t)node * CAP]);
    const float* scol = s + j;

    float a0 = 0.f, a1 = 0.f, a2 = 0.f, a3 = 0.f;
    const int iters = deg >> 3;          // full 8-edge groups

    float4 q0, q1, q2, q3;
    if (iters > 0) {
        q0 = __ldcs(el4 + 0);
        q1 = __ldcs(el4 + 1);
        q2 = __ldcs(el4 + 2);
        q3 = __ldcs(el4 + 3);
    }
    for (int it = 0; it < iters; it++) {
        float4 p0 = q0, p1 = q1, p2 = q2, p3 = q3;
        // unconditional prefetch (g_edges padded; extra values discarded)
        q0 = __ldcs(el4 + 4 * it + 4);
        q1 = __ldcs(el4 + 4 * it + 5);
        q2 = __ldcs(el4 + 4 * it + 6);
        q3 = __ldcs(el4 + 4 * it + 7);
        float r0 = __ldg(scol + (unsigned)__float_as_int(p0.y) * SIN);
        float r1 = __ldg(scol + (unsigned)__float_as_int(p0.w) * SIN);
        float r2 = __ldg(scol + (unsigned)__float_as_int(p1.y) * SIN);
        float r3 = __ldg(scol + (unsigned)__float_as_int(p1.w) * SIN);
        float r4 = __ldg(scol + (unsigned)__float_as_int(p2.y) * SIN);
        float r5 = __ldg(scol + (unsigned)__float_as_int(p2.w) * SIN);
        float r6 = __ldg(scol + (unsigned)__float_as_int(p3.y) * SIN);
        float r7 = __ldg(scol + (unsigned)__float_as_int(p3.w) * SIN);
        a0 = fmaf(p0.x, r0, a0);
        a1 = fmaf(p0.z, r1, a1);
        a2 = fmaf(p1.x, r2, a2);
        a3 = fmaf(p1.z, r3, a3);
        a0 = fmaf(p2.x, r4, a0);
        a1 = fmaf(p2.z, r5, a1);
        a2 = fmaf(p3.x, r6, a2);
        a3 = fmaf(p3.z, r7, a3);
    }
    for (int e = iters << 3; e < deg; e++) {
        float2 ed = g_edges[(size_t)node * CAP + e];
        a0 = fmaf(ed.x, __ldg(scol + (unsigned)__float_as_int(ed.y) * SIN), a0);
    }
    float acc = (a0 + a1) + (a2 + a3);

    // epilogue: bias + activation on owned feature
    float h = acc;
    if (j < DIN) {
        if (BPRE) h += sbpre[j];
        if (ACT == 1) h = fmaxf(h, 0.f);
        else if (ACT == 2) h = h - tanhf(h);
    } else {
        h = 0.f;
    }

    if (!GEMM) {
        if (valid && j < DIN) out[(size_t)node * SOUT + j] = h;
        return;
    }

    sh[warpid][sub][j] = h;
    __syncwarp();

    if (valid) {
#pragma unroll
        for (int jo = j; jo < DOUT; jo += SUB) {
            float a = BPOST ? sbpost[jo] : 0.f;
#pragma unroll
            for (int k = 0; k < DIN; k++)
                a = fmaf(sh[warpid][sub][k], sW[k * DOUT + jo], a);
            out[(size_t)node * SOUT + jo] = a;
        }
    }
}

// ---------------------------------------------------------------------------
// Launch
// ---------------------------------------------------------------------------
extern "C" void kernel_launch(void* const* d_in, const int* in_sizes, int n_in,
                              void* d_out, int out_size) {
    const float* x = nullptr;
    const float* ev = nullptr;
    const int* esrc = nullptr;
    const int* edst = nullptr;
    const float* W[6] = {0};
    const float* b[6] = {0};
    const int wsz[6] = {512 * 12, 12 * 10, 10 * 8, 8 * 6, 6 * 4, 4 * 7};
    const int bsz[6] = {12, 10, 8, 6, 4, 7};

    int edgeSeen = 0;
    for (int i = 0; i < n_in; i++) {
        int sz = in_sizes[i];
        if (sz == N_NODES * 512) {
            x = (const float*)d_in[i];
        } else if (sz == N_EDGES) {
            if (edgeSeen == 0) ev = (const float*)d_in[i];
            else if (edgeSeen == 1) esrc = (const int*)d_in[i];
            else edst = (const int*)d_in[i];
            edgeSeen++;
        } else {
            for (int j = 0; j < 6; j++) {
                if (sz == wsz[j]) W[j] = (const float*)d_in[i];
                else if (sz == bsz[j]) b[j] = (const float*)d_in[i];
            }
        }
    }

    float* bufA = nullptr;
    float* bufB = nullptr;
    int* cursor = nullptr;
    cudaGetSymbolAddress((void**)&bufA, g_bufA);
    cudaGetSymbolAddress((void**)&bufB, g_bufB);
    cudaGetSymbolAddress((void**)&cursor, g_cursor);
    float* out = (float*)d_out;

    const int TB = 256;
    auto blocks = [](long long n, int tb) { return (int)((n + tb - 1) / tb); };

    // warp-per-row grid for mm1
    const int WB = blocks((long long)N_NODES * 32, TB);
    // sub-warp grids: threads = ceil(N/NPW) warps * 32
    auto gridFor = [&](int NPW) {
        long long warps = (N_NODES + NPW - 1) / NPW;
        return blocks(warps * 32, TB);
    };

    // Build dst bins (once per launch)
    cudaMemsetAsync(cursor, 0, (size_t)N_NODES * sizeof(int));
    fill_bins_kernel<<<blocks((N_EDGES + 3) / 4, TB), TB>>>(ev, esrc, edst);

    // s1 = x @ W1  (12 wide, stride 16) -> bufA
    mm1_kernel<<<WB, TB>>>(x, W[0], bufA);

    // p1: h1 = agg(s1)+b1 ; s2 = h1@W2         (DIN=12 SUB=16 SIN=16 -> 10w s16)
    gather_kernel<12, 16, 16, 10, 16, 0, true, true, false>
        <<<gridFor(2), TB>>>(bufA, W[1], b[0], nullptr, bufB);
    // p2: h2 = relu(agg(s2)+b2) ; s3 = h2@W3   (DIN=10 SUB=16 SIN=16 -> 8w s8)
    gather_kernel<10, 16, 16, 8, 8, 1, true, true, false>
        <<<gridFor(2), TB>>>(bufB, W[2], b[1], nullptr, bufA);
    // p3: h3 = ts(agg(s3)+b3) ; s4 = h3@W4     (DIN=8 SUB=8 SIN=8 -> 6w s8)
    gather_kernel<8, 8, 8, 6, 8, 2, true, true, false>
        <<<gridFor(4), TB>>>(bufA, W[3], b[2], nullptr, bufB);
    // p4: h4 = ts(agg(s4)+b4) ; s5 = h4@W5     (DIN=6 SUB=8 SIN=8 -> 4w s4)
    gather_kernel<6, 8, 8, 4, 4, 2, true, true, false>
        <<<gridFor(4), TB>>>(bufB, W[4], b[3], nullptr, bufA);
    // p5: h5 = agg(s5)+b5                      (DIN=4 SUB=4 SIN=4 -> 4w s4, no GEMM)
    gather_kernel<4, 4, 4, 1, 4, 0, true, false, false>
        <<<gridFor(8), TB>>>(bufA, nullptr, b[4], nullptr, bufB);
    // p6: out = (agg(h5))@W6 + b6              (DIN=4 SUB=4 SIN=4 -> 7w packed)
    gather_kernel<4, 4, 4, 7, 7, 0, false, true, true>
        <<<gridFor(8), TB>>>(bufB, W[5], nullptr, b[5], out);

    (void)out_size;
}

// round 10
// speedup vs baseline: 1.1048x; 1.1048x over previous
#include <cuda_runtime.h>
#include <math.h>

#define N_NODES 100000
#define N_EDGES 3200000
#define CAP 96          // max in-degree slots (Poisson(32): P(deg>96) ~ 1e-20)

// Scratch (static device globals; no allocation). Max stride 16 floats.
__device__ __align__(128) float g_bufA[(size_t)N_NODES * 16];
__device__ __align__(128) float g_bufB[(size_t)N_NODES * 16];
__device__ int    g_cursor[N_NODES];
__device__ __align__(128) float2 g_edges[(size_t)(N_NODES + 1) * CAP];

// ---------------------------------------------------------------------------
// Layer-1 dense MM: s1[100000,12] = x[100000,512] @ W1[512,12]  (stride 16 out)
// ---------------------------------------------------------------------------
__global__ void mm1_kernel(const float* __restrict__ x,
                           const float* __restrict__ W,
                           float* __restrict__ out) {
    __shared__ float sW[512 * 13];
    for (int i = threadIdx.x; i < 512 * 12; i += blockDim.x) {
        int k = i / 12, j = i % 12;
        sW[k * 13 + j] = W[i];
    }
    __syncthreads();

    int warp = (blockIdx.x * blockDim.x + threadIdx.x) >> 5;
    int lane = threadIdx.x & 31;
    if (warp >= N_NODES) return;

    const float4* xr = reinterpret_cast<const float4*>(x + (size_t)warp * 512);
    float acc[12];
#pragma unroll
    for (int j = 0; j < 12; j++) acc[j] = 0.f;

#pragma unroll
    for (int it = 0; it < 4; it++) {
        int k4 = it * 32 + lane;
        float4 xv = xr[k4];
        int k = k4 * 4;
#pragma unroll
        for (int j = 0; j < 12; j++) {
            acc[j] = fmaf(xv.x, sW[(k + 0) * 13 + j], acc[j]);
            acc[j] = fmaf(xv.y, sW[(k + 1) * 13 + j], acc[j]);
            acc[j] = fmaf(xv.z, sW[(k + 2) * 13 + j], acc[j]);
            acc[j] = fmaf(xv.w, sW[(k + 3) * 13 + j], acc[j]);
        }
    }
#pragma unroll
    for (int j = 0; j < 12; j++) {
#pragma unroll
        for (int o = 16; o > 0; o >>= 1)
            acc[j] += __shfl_down_sync(0xffffffffu, acc[j], o);
    }
    if (lane == 0) {
        float* o = out + (size_t)warp * 16;
#pragma unroll
        for (int j = 0; j < 12; j++) o[j] = acc[j];
    }
}

// ---------------------------------------------------------------------------
// Bin edges by destination, 4 edges per thread (vector index loads).
// ---------------------------------------------------------------------------
__global__ void fill_bins_kernel(const float* __restrict__ ev,
                                 const int* __restrict__ src,
                                 const int* __restrict__ dst) {
    int t = blockIdx.x * blockDim.x + threadIdx.x;
    int e = t * 4;
    if (e + 4 <= N_EDGES) {
        float4 v4 = *reinterpret_cast<const float4*>(ev + e);
        int4 s4 = *reinterpret_cast<const int4*>(src + e);
        int4 d4 = *reinterpret_cast<const int4*>(dst + e);
        int p0 = atomicAdd(&g_cursor[d4.x], 1);
        int p1 = atomicAdd(&g_cursor[d4.y], 1);
        int p2 = atomicAdd(&g_cursor[d4.z], 1);
        int p3 = atomicAdd(&g_cursor[d4.w], 1);
        if (p0 < CAP) g_edges[(size_t)d4.x * CAP + p0] = make_float2(v4.x, __int_as_float(s4.x));
        if (p1 < CAP) g_edges[(size_t)d4.y * CAP + p1] = make_float2(v4.y, __int_as_float(s4.y));
        if (p2 < CAP) g_edges[(size_t)d4.z * CAP + p2] = make_float2(v4.z, __int_as_float(s4.z));
        if (p3 < CAP) g_edges[(size_t)d4.w * CAP + p3] = make_float2(v4.w, __int_as_float(s4.w));
    } else {
        for (; e < N_EDGES; e++) {
            int d = dst[e];
            int pos = atomicAdd(&g_cursor[d], 1);
            if (pos < CAP)
                g_edges[(size_t)d * CAP + pos] = make_float2(ev[e], __int_as_float(src[e]));
        }
    }
}

// ---------------------------------------------------------------------------
// Fused gather + epilogue. SUB lanes per node, lane j owns feature j.
// The node's packed edge list is first STAGED INTO SMEM (one streaming
// LDG.128+STS.128 loop), then the main loop reads edges via broadcast LDS and
// keeps 8 independent row LDGs in flight per lane with ~32 registers.
// Epilogue: h = ACT(agg [+ bpre]); out = GEMM ? h@W [+ bpost] : h.
// ACT: 0=id, 1=relu, 2=tanhshrink
// ---------------------------------------------------------------------------
template <int DIN, int SUB, int SIN, int DOUT, int SOUT,
          int ACT, bool BPRE, bool GEMM, bool BPOST>
__global__ void __launch_bounds__(256, 8)
gather_kernel(const float* __restrict__ s,
              const float* __restrict__ W,
              const float* __restrict__ bpre,
              const float* __restrict__ bpost,
              float* __restrict__ out) {
    constexpr int NPW = 32 / SUB;     // nodes per warp
    constexpr int N4 = CAP / 2;       // float4 slots per node (48)
    __shared__ float4 sel[8][NPW][N4 + 1];   // +1 float4 pad -> bank stagger
    __shared__ float sW[GEMM ? DIN * DOUT : 1];
    __shared__ float sbpre[DIN];
    __shared__ float sbpost[BPOST ? DOUT : 1];
    __shared__ float sh[8][NPW][SUB];

    if (GEMM)
        for (int i = threadIdx.x; i < DIN * DOUT; i += blockDim.x) sW[i] = W[i];
    if (BPRE && threadIdx.x < DIN) sbpre[threadIdx.x] = bpre[threadIdx.x];
    if (BPOST && threadIdx.x < DOUT) sbpost[threadIdx.x] = bpost[threadIdx.x];
    __syncthreads();

    const int warpid = threadIdx.x >> 5;
    const int lane = threadIdx.x & 31;
    const int sub = lane / SUB;          // node slot within warp
    const int j = lane & (SUB - 1);      // owned feature lane
    const int node = ((blockIdx.x * blockDim.x + threadIdx.x) >> 5) * NPW + sub;
    const bool valid = node < N_NODES;

    int deg = 0;
    if (valid) {
        deg = g_cursor[node];
        deg = deg < CAP ? deg : CAP;
    }

    // stage packed edge list into smem (SUB lanes cooperate per node)
    {
        const float4* el4 = reinterpret_cast<const float4*>(&g_edges[(size_t)node * CAP]);
        int n4 = (deg + 1) >> 1;         // float4 count covering deg edges
        for (int c = j; c < n4; c += SUB)
            sel[warpid][sub][c] = __ldcs(el4 + c);
    }
    __syncwarp();

    // clamp feature lane for row loads (extra lanes broadcast feature 0)
    const unsigned joff = (j < DIN) ? (unsigned)j : 0u;
    const float* scol = s + joff;
    const float4* myel = sel[warpid][sub];

    float a0 = 0.f, a1 = 0.f, a2 = 0.f, a3 = 0.f;
    const int iters = deg >> 3;          // full 8-edge groups

    for (int it = 0; it < iters; it++) {
        float4 p0 = myel[4 * it + 0];
        float4 p1 = myel[4 * it + 1];
        float4 p2 = myel[4 * it + 2];
        float4 p3 = myel[4 * it + 3];
        float r0 = __ldg(scol + (unsigned)__float_as_int(p0.y) * SIN);
        float r1 = __ldg(scol + (unsigned)__float_as_int(p0.w) * SIN);
        float r2 = __ldg(scol + (unsigned)__float_as_int(p1.y) * SIN);
        float r3 = __ldg(scol + (unsigned)__float_as_int(p1.w) * SIN);
        float r4 = __ldg(scol + (unsigned)__float_as_int(p2.y) * SIN);
        float r5 = __ldg(scol + (unsigned)__float_as_int(p2.w) * SIN);
        float r6 = __ldg(scol + (unsigned)__float_as_int(p3.y) * SIN);
        float r7 = __ldg(scol + (unsigned)__float_as_int(p3.w) * SIN);
        a0 = fmaf(p0.x, r0, a0);
        a1 = fmaf(p0.z, r1, a1);
        a2 = fmaf(p1.x, r2, a2);
        a3 = fmaf(p1.z, r3, a3);
        a0 = fmaf(p2.x, r4, a0);
        a1 = fmaf(p2.z, r5, a1);
        a2 = fmaf(p3.x, r6, a2);
        a3 = fmaf(p3.z, r7, a3);
    }
    // tail (< 8 edges) from smem
    {
        const float2* selt = reinterpret_cast<const float2*>(myel);
        for (int e = iters << 3; e < deg; e++) {
            float2 ed = selt[e];
            a0 = fmaf(ed.x, __ldg(scol + (unsigned)__float_as_int(ed.y) * SIN), a0);
        }
    }
    float acc = (a0 + a1) + (a2 + a3);

    // epilogue: bias + activation on owned feature
    float h = acc;
    if (j < DIN) {
        if (BPRE) h += sbpre[j];
        if (ACT == 1) h = fmaxf(h, 0.f);
        else if (ACT == 2) h = h - tanhf(h);
    } else {
        h = 0.f;
    }

    if (!GEMM) {
        if (valid && j < DIN) out[(size_t)node * SOUT + j] = h;
        return;
    }

    if (j < SUB) sh[warpid][sub][j] = h;
    __syncwarp();

    if (valid) {
#pragma unroll
        for (int jo = j; jo < DOUT; jo += SUB) {
            float a = BPOST ? sbpost[jo] : 0.f;
#pragma unroll
            for (int k = 0; k < DIN; k++)
                a = fmaf(sh[warpid][sub][k], sW[k * DOUT + jo], a);
            out[(size_t)node * SOUT + jo] = a;
        }
    }
}

// ---------------------------------------------------------------------------
// Launch
// ---------------------------------------------------------------------------
extern "C" void kernel_launch(void* const* d_in, const int* in_sizes, int n_in,
                              void* d_out, int out_size) {
    const float* x = nullptr;
    const float* ev = nullptr;
    const int* esrc = nullptr;
    const int* edst = nullptr;
    const float* W[6] = {0};
    const float* b[6] = {0};
    const int wsz[6] = {512 * 12, 12 * 10, 10 * 8, 8 * 6, 6 * 4, 4 * 7};
    const int bsz[6] = {12, 10, 8, 6, 4, 7};

    int edgeSeen = 0;
    for (int i = 0; i < n_in; i++) {
        int sz = in_sizes[i];
        if (sz == N_NODES * 512) {
            x = (const float*)d_in[i];
        } else if (sz == N_EDGES) {
            if (edgeSeen == 0) ev = (const float*)d_in[i];
            else if (edgeSeen == 1) esrc = (const int*)d_in[i];
            else edst = (const int*)d_in[i];
            edgeSeen++;
        } else {
            for (int j = 0; j < 6; j++) {
                if (sz == wsz[j]) W[j] = (const float*)d_in[i];
                else if (sz == bsz[j]) b[j] = (const float*)d_in[i];
            }
        }
    }

    float* bufA = nullptr;
    float* bufB = nullptr;
    int* cursor = nullptr;
    cudaGetSymbolAddress((void**)&bufA, g_bufA);
    cudaGetSymbolAddress((void**)&bufB, g_bufB);
    cudaGetSymbolAddress((void**)&cursor, g_cursor);
    float* out = (float*)d_out;

    const int TB = 256;
    auto blocks = [](long long n, int tb) { return (int)((n + tb - 1) / tb); };

    // warp-per-row grid for mm1
    const int WB = blocks((long long)N_NODES * 32, TB);
    // sub-warp grids: threads = ceil(N/NPW) warps * 32
    auto gridFor = [&](int NPW) {
        long long warps = (N_NODES + NPW - 1) / NPW;
        return blocks(warps * 32, TB);
    };

    // Build dst bins (once per launch)
    cudaMemsetAsync(cursor, 0, (size_t)N_NODES * sizeof(int));
    fill_bins_kernel<<<blocks((N_EDGES + 3) / 4, TB), TB>>>(ev, esrc, edst);

    // s1 = x @ W1  (12 wide, stride 16) -> bufA
    mm1_kernel<<<WB, TB>>>(x, W[0], bufA);

    // p1: h1 = agg(s1)+b1 ; s2 = h1@W2         (DIN=12 SUB=16 SIN=16 -> 10w s16)
    gather_kernel<12, 16, 16, 10, 16, 0, true, true, false>
        <<<gridFor(2), TB>>>(bufA, W[1], b[0], nullptr, bufB);
    // p2: h2 = relu(agg(s2)+b2) ; s3 = h2@W3   (DIN=10 SUB=16 SIN=16 -> 8w s8)
    gather_kernel<10, 16, 16, 8, 8, 1, true, true, false>
        <<<gridFor(2), TB>>>(bufB, W[2], b[1], nullptr, bufA);
    // p3: h3 = ts(agg(s3)+b3) ; s4 = h3@W4     (DIN=8 SUB=8 SIN=8 -> 6w s8)
    gather_kernel<8, 8, 8, 6, 8, 2, true, true, false>
        <<<gridFor(4), TB>>>(bufA, W[3], b[2], nullptr, bufB);
    // p4: h4 = ts(agg(s4)+b4) ; s5 = h4@W5     (DIN=6 SUB=8 SIN=8 -> 4w s4)
    gather_kernel<6, 8, 8, 4, 4, 2, true, true, false>
        <<<gridFor(4), TB>>>(bufB, W[4], b[3], nullptr, bufA);
    // p5: h5 = agg(s5)+b5                      (DIN=4 SUB=8 SIN=4 -> 4w s4, no GEMM)
    gather_kernel<4, 8, 4, 4, 4, 0, true, false, false>
        <<<gridFor(4), TB>>>(bufA, nullptr, b[4], nullptr, bufB);
    // p6: out = (agg(h5))@W6 + b6              (DIN=4 SUB=8 SIN=4 -> 7w packed)
    gather_kernel<4, 8, 4, 7, 7, 0, false, true, true>
        <<<gridFor(4), TB>>>(bufB, W[5], nullptr, b[5], out);

    (void)out_size;
}

// round 11
// speedup vs baseline: 1.2270x; 1.1106x over previous
#include <cuda_runtime.h>
#include <math.h>

#define N_NODES 100000
#define N_EDGES 3200000
#define CAP 96          // max in-degree slots (Poisson(32): P(deg>96) ~ 1e-20)

// Scratch (static device globals; no allocation). Max stride 16 floats.
__device__ __align__(128) float g_bufA[(size_t)N_NODES * 16];
__device__ __align__(128) float g_bufB[(size_t)N_NODES * 16];
__device__ int    g_cursor[N_NODES];
// +1 node padding: register-pipelined prefetch may read past the last bin
__device__ __align__(128) float2 g_edges[(size_t)(N_NODES + 1) * CAP];

// ---------------------------------------------------------------------------
// Layer-1 dense MM: s1[100000,12] = x[100000,512] @ W1[512,12]  (stride 16 out)
// ---------------------------------------------------------------------------
__global__ void mm1_kernel(const float* __restrict__ x,
                           const float* __restrict__ W,
                           float* __restrict__ out) {
    __shared__ float sW[512 * 13];
    for (int i = threadIdx.x; i < 512 * 12; i += blockDim.x) {
        int k = i / 12, j = i % 12;
        sW[k * 13 + j] = W[i];
    }
    __syncthreads();

    int warp = (blockIdx.x * blockDim.x + threadIdx.x) >> 5;
    int lane = threadIdx.x & 31;
    if (warp >= N_NODES) return;

    const float4* xr = reinterpret_cast<const float4*>(x + (size_t)warp * 512);
    float acc[12];
#pragma unroll
    for (int j = 0; j < 12; j++) acc[j] = 0.f;

#pragma unroll
    for (int it = 0; it < 4; it++) {
        int k4 = it * 32 + lane;
        float4 xv = xr[k4];
        int k = k4 * 4;
#pragma unroll
        for (int j = 0; j < 12; j++) {
            acc[j] = fmaf(xv.x, sW[(k + 0) * 13 + j], acc[j]);
            acc[j] = fmaf(xv.y, sW[(k + 1) * 13 + j], acc[j]);
            acc[j] = fmaf(xv.z, sW[(k + 2) * 13 + j], acc[j]);
            acc[j] = fmaf(xv.w, sW[(k + 3) * 13 + j], acc[j]);
        }
    }
#pragma unroll
    for (int j = 0; j < 12; j++) {
#pragma unroll
        for (int o = 16; o > 0; o >>= 1)
            acc[j] += __shfl_down_sync(0xffffffffu, acc[j], o);
    }
    if (lane == 0) {
        float* o = out + (size_t)warp * 16;
#pragma unroll
        for (int j = 0; j < 12; j++) o[j] = acc[j];
    }
}

// ---------------------------------------------------------------------------
// Bin edges by destination, 4 edges per thread (vector index loads).
// ---------------------------------------------------------------------------
__global__ void fill_bins_kernel(const float* __restrict__ ev,
                                 const int* __restrict__ src,
                                 const int* __restrict__ dst) {
    int t = blockIdx.x * blockDim.x + threadIdx.x;
    int e = t * 4;
    if (e + 4 <= N_EDGES) {
        float4 v4 = *reinterpret_cast<const float4*>(ev + e);
        int4 s4 = *reinterpret_cast<const int4*>(src + e);
        int4 d4 = *reinterpret_cast<const int4*>(dst + e);
        int p0 = atomicAdd(&g_cursor[d4.x], 1);
        int p1 = atomicAdd(&g_cursor[d4.y], 1);
        int p2 = atomicAdd(&g_cursor[d4.z], 1);
        int p3 = atomicAdd(&g_cursor[d4.w], 1);
        if (p0 < CAP) g_edges[(size_t)d4.x * CAP + p0] = make_float2(v4.x, __int_as_float(s4.x));
        if (p1 < CAP) g_edges[(size_t)d4.y * CAP + p1] = make_float2(v4.y, __int_as_float(s4.y));
        if (p2 < CAP) g_edges[(size_t)d4.z * CAP + p2] = make_float2(v4.z, __int_as_float(s4.z));
        if (p3 < CAP) g_edges[(size_t)d4.w * CAP + p3] = make_float2(v4.w, __int_as_float(s4.w));
    } else {
        for (; e < N_EDGES; e++) {
            int d = dst[e];
            int pos = atomicAdd(&g_cursor[d], 1);
            if (pos < CAP)
                g_edges[(size_t)d * CAP + pos] = make_float2(ev[e], __int_as_float(src[e]));
        }
    }
}

// ---------------------------------------------------------------------------
// STAGED gather (wide layers, SUB=16/NPW=2): edge list staged into smem with
// cached loads (L2-persistent across passes), then 8 row-LDGs in flight/lane.
// ---------------------------------------------------------------------------
template <int DIN, int SUB, int SIN, int DOUT, int SOUT,
          int ACT, bool BPRE, bool GEMM, bool BPOST>
__global__ void __launch_bounds__(256, 8)
gather_staged_kernel(const float* __restrict__ s,
                     const float* __restrict__ W,
                     const float* __restrict__ bpre,
                     const float* __restrict__ bpost,
                     float* __restrict__ out) {
    constexpr int NPW = 32 / SUB;     // nodes per warp
    constexpr int N4 = CAP / 2;       // float4 slots per node (48)
    __shared__ float4 sel[8][NPW][N4 + 1];
    __shared__ float sW[GEMM ? DIN * DOUT : 1];
    __shared__ float sbpre[DIN];
    __shared__ float sbpost[BPOST ? DOUT : 1];
    __shared__ float sh[8][NPW][SUB];

    if (GEMM)
        for (int i = threadIdx.x; i < DIN * DOUT; i += blockDim.x) sW[i] = W[i];
    if (BPRE && threadIdx.x < DIN) sbpre[threadIdx.x] = bpre[threadIdx.x];
    if (BPOST && threadIdx.x < DOUT) sbpost[threadIdx.x] = bpost[threadIdx.x];
    __syncthreads();

    const int warpid = threadIdx.x >> 5;
    const int lane = threadIdx.x & 31;
    const int sub = lane / SUB;
    const int j = lane & (SUB - 1);
    const int node = ((blockIdx.x * blockDim.x + threadIdx.x) >> 5) * NPW + sub;
    const bool valid = node < N_NODES;

    int deg = 0;
    if (valid) {
        deg = g_cursor[node];
        deg = deg < CAP ? deg : CAP;
    }

    // stage packed edge list into smem (cached loads -> L2-resident for later passes)
    {
        const float4* el4 = reinterpret_cast<const float4*>(&g_edges[(size_t)node * CAP]);
        int n4 = (deg + 1) >> 1;
        for (int c = j; c < n4; c += SUB)
            sel[warpid][sub][c] = __ldg(el4 + c);
    }
    __syncwarp();

    const unsigned joff = (j < DIN) ? (unsigned)j : 0u;
    const float* scol = s + joff;
    const float4* myel = sel[warpid][sub];

    float a0 = 0.f, a1 = 0.f, a2 = 0.f, a3 = 0.f;
    const int iters = deg >> 3;

    for (int it = 0; it < iters; it++) {
        float4 p0 = myel[4 * it + 0];
        float4 p1 = myel[4 * it + 1];
        float4 p2 = myel[4 * it + 2];
        float4 p3 = myel[4 * it + 3];
        float r0 = __ldg(scol + (unsigned)__float_as_int(p0.y) * SIN);
        float r1 = __ldg(scol + (unsigned)__float_as_int(p0.w) * SIN);
        float r2 = __ldg(scol + (unsigned)__float_as_int(p1.y) * SIN);
        float r3 = __ldg(scol + (unsigned)__float_as_int(p1.w) * SIN);
        float r4 = __ldg(scol + (unsigned)__float_as_int(p2.y) * SIN);
        float r5 = __ldg(scol + (unsigned)__float_as_int(p2.w) * SIN);
        float r6 = __ldg(scol + (unsigned)__float_as_int(p3.y) * SIN);
        float r7 = __ldg(scol + (unsigned)__float_as_int(p3.w) * SIN);
        a0 = fmaf(p0.x, r0, a0);
        a1 = fmaf(p0.z, r1, a1);
        a2 = fmaf(p1.x, r2, a2);
        a3 = fmaf(p1.z, r3, a3);
        a0 = fmaf(p2.x, r4, a0);
        a1 = fmaf(p2.z, r5, a1);
        a2 = fmaf(p3.x, r6, a2);
        a3 = fmaf(p3.z, r7, a3);
    }
    {
        const float2* selt = reinterpret_cast<const float2*>(myel);
        for (int e = iters << 3; e < deg; e++) {
            float2 ed = selt[e];
            a0 = fmaf(ed.x, __ldg(scol + (unsigned)__float_as_int(ed.y) * SIN), a0);
        }
    }
    float acc = (a0 + a1) + (a2 + a3);

    float h = acc;
    if (j < DIN) {
        if (BPRE) h += sbpre[j];
        if (ACT == 1) h = fmaxf(h, 0.f);
        else if (ACT == 2) h = h - tanhf(h);
    } else {
        h = 0.f;
    }

    if (!GEMM) {
        if (valid && j < DIN) out[(size_t)node * SOUT + j] = h;
        return;
    }

    sh[warpid][sub][j] = h;
    __syncwarp();

    if (valid) {
#pragma unroll
        for (int jo = j; jo < DOUT; jo += SUB) {
            float a = BPOST ? sbpost[jo] : 0.f;
#pragma unroll
            for (int k = 0; k < DIN; k++)
                a = fmaf(sh[warpid][sub][k], sW[k * DOUT + jo], a);
            out[(size_t)node * SOUT + jo] = a;
        }
    }
}

// ---------------------------------------------------------------------------
// REGISTER-PIPELINED gather (narrow layers): unroll-4 with elist prefetch
// (R8 structure, proven at 338us). Cached elist loads for L2 persistence.
// ---------------------------------------------------------------------------
template <int DIN, int SUB, int SIN, int DOUT, int SOUT,
          int ACT, bool BPRE, bool GEMM, bool BPOST>
__global__ void __launch_bounds__(256, 6)
gather_reg_kernel(const float* __restrict__ s,
                  const float* __restrict__ W,
                  const float* __restrict__ bpre,
                  const float* __restrict__ bpost,
                  float* __restrict__ out) {
    constexpr int NPW = 32 / SUB;
    __shared__ float sW[GEMM ? DIN * DOUT : 1];
    __shared__ float sbpre[DIN];
    __shared__ float sbpost[BPOST ? DOUT : 1];
    __shared__ float sh[8][NPW][SUB];

    if (GEMM)
        for (int i = threadIdx.x; i < DIN * DOUT; i += blockDim.x) sW[i] = W[i];
    if (BPRE && threadIdx.x < DIN) sbpre[threadIdx.x] = bpre[threadIdx.x];
    if (BPOST && threadIdx.x < DOUT) sbpost[threadIdx.x] = bpost[threadIdx.x];
    __syncthreads();

    const int warpid = threadIdx.x >> 5;
    const int lane = threadIdx.x & 31;
    const int sub = lane / SUB;
    const int j = lane & (SUB - 1);
    const int node = ((blockIdx.x * blockDim.x + threadIdx.x) >> 5) * NPW + sub;
    const bool valid = node < N_NODES;

    int deg = 0;
    if (valid) {
        deg = g_cursor[node];
        deg = deg < CAP ? deg : CAP;
    }

    const float4* el4 = reinterpret_cast<const float4*>(&g_edges[(size_t)node * CAP]);
    const unsigned joff = (j < DIN) ? (unsigned)j : 0u;
    const float* scol = s + joff;

    float a0 = 0.f, a1 = 0.f, a2 = 0.f, a3 = 0.f;
    const int iters = deg >> 2;

    float4 q0, q1;
    if (iters > 0) { q0 = __ldg(el4 + 0); q1 = __ldg(el4 + 1); }
    for (int it = 0; it < iters; it++) {
        float4 p0 = q0, p1 = q1;
        q0 = __ldg(el4 + 2 * it + 2);
        q1 = __ldg(el4 + 2 * it + 3);
        float r0 = __ldg(scol + (unsigned)__float_as_int(p0.y) * SIN);
        float r1 = __ldg(scol + (unsigned)__float_as_int(p0.w) * SIN);
        float r2 = __ldg(scol + (unsigned)__float_as_int(p1.y) * SIN);
        float r3 = __ldg(scol + (unsigned)__float_as_int(p1.w) * SIN);
        a0 = fmaf(p0.x, r0, a0);
        a1 = fmaf(p0.z, r1, a1);
        a2 = fmaf(p1.x, r2, a2);
        a3 = fmaf(p1.z, r3, a3);
    }
    for (int e = iters << 2; e < deg; e++) {
        float2 ed = g_edges[(size_t)node * CAP + e];
        a0 = fmaf(ed.x, __ldg(scol + (unsigned)__float_as_int(ed.y) * SIN), a0);
    }
    float acc = (a0 + a1) + (a2 + a3);

    float h = acc;
    if (j < DIN) {
        if (BPRE) h += sbpre[j];
        if (ACT == 1) h = fmaxf(h, 0.f);
        else if (ACT == 2) h = h - tanhf(h);
    } else {
        h = 0.f;
    }

    if (!GEMM) {
        if (valid && j < DIN) out[(size_t)node * SOUT + j] = h;
        return;
    }

    sh[warpid][sub][j] = h;
    __syncwarp();

    if (valid) {
#pragma unroll
        for (int jo = j; jo < DOUT; jo += SUB) {
            float a = BPOST ? sbpost[jo] : 0.f;
#pragma unroll
            for (int k = 0; k < DIN; k++)
                a = fmaf(sh[warpid][sub][k], sW[k * DOUT + jo], a);
            out[(size_t)node * SOUT + jo] = a;
        }
    }
}

// ---------------------------------------------------------------------------
// Launch
// ---------------------------------------------------------------------------
extern "C" void kernel_launch(void* const* d_in, const int* in_sizes, int n_in,
                              void* d_out, int out_size) {
    const float* x = nullptr;
    const float* ev = nullptr;
    const int* esrc = nullptr;
    const int* edst = nullptr;
    const float* W[6] = {0};
    const float* b[6] = {0};
    const int wsz[6] = {512 * 12, 12 * 10, 10 * 8, 8 * 6, 6 * 4, 4 * 7};
    const int bsz[6] = {12, 10, 8, 6, 4, 7};

    int edgeSeen = 0;
    for (int i = 0; i < n_in; i++) {
        int sz = in_sizes[i];
        if (sz == N_NODES * 512) {
            x = (const float*)d_in[i];
        } else if (sz == N_EDGES) {
            if (edgeSeen == 0) ev = (const float*)d_in[i];
            else if (edgeSeen == 1) esrc = (const int*)d_in[i];
            else edst = (const int*)d_in[i];
            edgeSeen++;
        } else {
            for (int j = 0; j < 6; j++) {
                if (sz == wsz[j]) W[j] = (const float*)d_in[i];
                else if (sz == bsz[j]) b[j] = (const float*)d_in[i];
            }
        }
    }

    float* bufA = nullptr;
    float* bufB = nullptr;
    int* cursor = nullptr;
    cudaGetSymbolAddress((void**)&bufA, g_bufA);
    cudaGetSymbolAddress((void**)&bufB, g_bufB);
    cudaGetSymbolAddress((void**)&cursor, g_cursor);
    float* out = (float*)d_out;

    const int TB = 256;
    auto blocks = [](long long n, int tb) { return (int)((n + tb - 1) / tb); };

    const int WB = blocks((long long)N_NODES * 32, TB);
    auto gridFor = [&](int NPW) {
        long long warps = (N_NODES + NPW - 1) / NPW;
        return blocks(warps * 32, TB);
    };

    // Build dst bins (once per launch)
    cudaMemsetAsync(cursor, 0, (size_t)N_NODES * sizeof(int));
    fill_bins_kernel<<<blocks((N_EDGES + 3) / 4, TB), TB>>>(ev, esrc, edst);

    // s1 = x @ W1  (12 wide, stride 16) -> bufA
    mm1_kernel<<<WB, TB>>>(x, W[0], bufA);

    // p1: h1 = agg(s1)+b1 ; s2 = h1@W2         (DIN=12 SUB=16 SIN=16 -> 10w s16)
    gather_staged_kernel<12, 16, 16, 10, 16, 0, true, true, false>
        <<<gridFor(2), TB>>>(bufA, W[1], b[0], nullptr, bufB);
    // p2: h2 = relu(agg(s2)+b2) ; s3 = h2@W3   (DIN=10 SUB=16 SIN=16 -> 8w s8)
    gather_staged_kernel<10, 16, 16, 8, 8, 1, true, true, false>
        <<<gridFor(2), TB>>>(bufB, W[2], b[1], nullptr, bufA);
    // p3: h3 = ts(agg(s3)+b3) ; s4 = h3@W4     (DIN=8 SUB=8 SIN=8 -> 6w s8)
    gather_reg_kernel<8, 8, 8, 6, 8, 2, true, true, false>
        <<<gridFor(4), TB>>>(bufA, W[3], b[2], nullptr, bufB);
    // p4: h4 = ts(agg(s4)+b4) ; s5 = h4@W5     (DIN=6 SUB=8 SIN=8 -> 4w s4)
    gather_reg_kernel<6, 8, 8, 4, 4, 2, true, true, false>
        <<<gridFor(4), TB>>>(bufB, W[4], b[3], nullptr, bufA);
    // p5: h5 = agg(s5)+b5                      (DIN=4 SUB=4 SIN=4 -> 4w s4, no GEMM)
    gather_reg_kernel<4, 4, 4, 4, 4, 0, true, false, false>
        <<<gridFor(8), TB>>>(bufA, nullptr, b[4], nullptr, bufB);
    // p6: out = (agg(h5))@W6 + b6              (DIN=4 SUB=4 SIN=4 -> 7w packed)
    gather_reg_kernel<4, 4, 4, 7, 7, 0, false, true, true>
        <<<gridFor(8), TB>>>(bufB, W[5], nullptr, b[5], out);

    (void)out_size;
}